// round 2
// baseline (speedup 1.0000x reference)
#include <cuda_runtime.h>
#include <cstdint>
#include <math.h>

#define Hdim 2048
#define Bdim 16
#define Tdim 1024
#define NIN 8
#define NOUT 8
#define TUNED 10
#define NCTA 128
#define RPC 16
#define NTH 256
#define KC 512
#define NCH 4
#define DTC 0.001f
#define TAUC 0.01f
#define BETAC 1.5f

// device-global scratch (static allocations are allowed)
__device__ float g_Wm[Hdim * Hdim];           // masked recurrent weights [j][k]
__device__ float g_v[2][Bdim * Hdim];         // v = r * tanh(h), double buffered
__device__ float g_zp[2][NCTA * Bdim * NOUT]; // per-CTA z partials, double buffered
__device__ unsigned g_arrive, g_gen;

__device__ __forceinline__ void cp16(float* d, const float* s) {
    unsigned ds = (unsigned)__cvta_generic_to_shared(d);
    asm volatile("cp.async.cg.shared.global [%0],[%1],16;" ::"r"(ds), "l"(s));
}

// accurate tanh independent of fast-math flags: tanh(x)=sign(x)*(1-2/(e^{2|x|}+1))
__device__ __forceinline__ float my_tanh(float x) {
    float ax = fabsf(x);
    float e;
    asm("ex2.approx.f32 %0, %1;" : "=f"(e) : "f"(ax * 2.8853900817779268f));
    float r = 1.0f - __fdiv_rn(2.0f, e + 1.0f);
    return x < 0.0f ? -r : r;
}

__device__ __forceinline__ void gbar(unsigned n) {
    __syncthreads();
    if (threadIdx.x == 0) {
        __threadfence();
        unsigned prev = atomicAdd(&g_arrive, 1u);
        if (prev == n * (unsigned)NCTA - 1u) {
            atomicAdd(&g_gen, 1u);
        } else {
            unsigned g;
            do {
                asm volatile("ld.acquire.gpu.u32 %0,[%1];" : "=r"(g) : "l"(&g_gen));
            } while (g < n);
        }
    }
    __syncthreads();
}

__global__ void build_wm(const float* __restrict__ wt, const float* __restrict__ wf,
                         const float* __restrict__ mk) {
    if (blockIdx.x == 0 && threadIdx.x == 0) { g_arrive = 0u; g_gen = 0u; }
    int idx = blockIdx.x * 256 + threadIdx.x;
    if (idx < Hdim * Hdim) {
        int j = idx >> 11, k = idx & (Hdim - 1);
        float w = (k < TUNED) ? wt[j * TUNED + k] : wf[j * (Hdim - TUNED) + (k - TUNED)];
        g_Wm[idx] = mk[idx] * w;
    }
}

__device__ __forceinline__ void prefetch(float* sV, const float* vsrc, int c, int tid) {
    float* dst = sV + (c & 1) * (Bdim * KC);
    const float* src = vsrc + c * KC;
#pragma unroll
    for (int u = 0; u < 8; u++) {
        int seg = u * NTH + tid;          // 2048 segments of 16B
        int b = seg >> 7;                 // batch
        int f = (seg & 127) << 2;         // float offset within chunk row
        cp16(dst + b * KC + f, src + (size_t)b * Hdim + f);
    }
    asm volatile("cp.async.commit_group;" ::: "memory");
}

__global__ __launch_bounds__(NTH, 1) void rnn_persist(
    const float* __restrict__ x, const float* __restrict__ h0,
    const float* __restrict__ Wih, const float* __restrict__ Whz,
    const float* __restrict__ Wzh, const float* __restrict__ tau,
    float* __restrict__ out) {

    extern __shared__ float sm[];
    float* sWm = sm;              // 32768 floats
    float* sV  = sm + 32768;      // 16384
    float* sHT = sm + 49152;      // 256   [j*16+b]
    float* sZ  = sm + 49408;      // 128   [b*8+o]
    float* sX  = sm + 49536;      // 128   [b*8+i]
    float* sWi = sm + 49664;      // 128   [j*8+i]
    float* sWz = sm + 49792;      // 128   [j*8+o]
    float* sWo = sm + 49920;      // 128   [o*16+j]
    float* sTa = sm + 50048;      // 16

    const int tid = threadIdx.x;
    const int cta = blockIdx.x;
    const int l = tid & 31, w = tid >> 5;
    const int jl = ((w & 3) << 2) + (l >> 3);  // 0..15 local row (owner)
    const int b  = ((w >> 2) << 3) + (l & 7);  // 0..15 batch (owner)
    const int jbase = (w & 3) << 2, bbase = (w >> 2) << 3;
    const int jrow = cta * RPC;

    float* out_z = out;
    float* out_h = out + (size_t)Bdim * Tdim * NOUT;
    float* out_r = out_h + (size_t)Bdim * Tdim * Hdim;

    // ---- one-time loads ----
    {
        const float4* src = (const float4*)(g_Wm + (size_t)jrow * Hdim);
        float4* dst = (float4*)sWm;
#pragma unroll 8
        for (int i = tid; i < RPC * Hdim / 4; i += NTH) dst[i] = src[i];
    }
    if (tid < 128) {
        int jj = tid >> 3, ii = tid & 7;
        sWi[tid] = Wih[(jrow + jj) * NIN + ii];
        sWz[tid] = Wzh[(jrow + jj) * NOUT + ii];
        int oo = tid >> 4, j2 = tid & 15;
        sWo[tid] = Whz[oo * Hdim + jrow + j2];
    }
    if (tid < RPC) sTa[tid] = tau[jrow + tid];

    // ---- init state in registers (one (j,b) pair per thread) ----
    float h = h0[(size_t)b * Hdim + jrow + jl];
    float r = 1.0f;                 // P_REL
    float hT = my_tanh(h);
    __stcg(&g_v[0][b * Hdim + jrow + jl], hT);   // r0=1 -> v0 = tanh(h0)
    sHT[jl * 16 + b] = hT;
    __syncthreads();
    if (tid < 128) {
        int bb2 = tid >> 3, oo = tid & 7;
        float s = 0.f;
#pragma unroll
        for (int j2 = 0; j2 < RPC; j2++) s = fmaf(sHT[j2 * 16 + bb2], sWo[oo * 16 + j2], s);
        __stcg(&g_zp[0][cta * 128 + tid], s);
    }
    gbar(1u);

    // ---- time loop ----
    for (int t = 0; t < Tdim; t++) {
        const int cb = t & 1, nb = cb ^ 1;
        const float* vsrc = g_v[cb];
        prefetch(sV, vsrc, 0, tid);

        // x_t and z_{t-1} reduction (overlaps with cp.async of chunk 0)
        if (tid < 128) {
            sX[tid] = x[((size_t)(tid >> 3) * Tdim + t) * NIN + (tid & 7)];
            const float* zp = g_zp[cb] + tid;
            float s = 0.f;
#pragma unroll 8
            for (int c2 = 0; c2 < NCTA; c2++) s += __ldcg(zp + c2 * 128);
            sZ[tid] = s;
            if (cta == 0 && t > 0)
                out_z[((size_t)(tid >> 3) * Tdim + (t - 1)) * NOUT + (tid & 7)] = s;
        }

        // ---- matvec: 4 rows x 8 batches per thread, 32-way k split ----
        float acc[32];
#pragma unroll
        for (int i = 0; i < 32; i++) acc[i] = 0.f;

        for (int c = 0; c < NCH; c++) {
            if (c + 1 < NCH) {
                prefetch(sV, vsrc, c + 1, tid);
                asm volatile("cp.async.wait_group 1;" ::: "memory");
            } else {
                asm volatile("cp.async.wait_group 0;" ::: "memory");
            }
            __syncthreads();
            const float* Wp = sWm + jbase * Hdim + c * KC + (l << 2);
            const float* Vp = sV + (c & 1) * (Bdim * KC) + bbase * KC + (l << 2);
#pragma unroll
            for (int it = 0; it < 4; it++) {
                float4 wv[4], vv[8];
#pragma unroll
                for (int rr = 0; rr < 4; rr++) wv[rr] = *(const float4*)(Wp + rr * Hdim + it * 128);
#pragma unroll
                for (int q = 0; q < 8; q++) vv[q] = *(const float4*)(Vp + q * KC + it * 128);
#pragma unroll
                for (int rr = 0; rr < 4; rr++)
#pragma unroll
                    for (int q = 0; q < 8; q++) {
                        float a = acc[rr * 8 + q];
                        a = fmaf(wv[rr].x, vv[q].x, a);
                        a = fmaf(wv[rr].y, vv[q].y, a);
                        a = fmaf(wv[rr].z, vv[q].z, a);
                        a = fmaf(wv[rr].w, vv[q].w, a);
                        acc[rr * 8 + q] = a;
                    }
            }
            __syncthreads();
        }

        // ---- merge-reduce: lane l ends holding total for accumulator index l ----
#pragma unroll
        for (int k = 0; k < 5; k++) {
            const int m = 1 << k;
            const bool s = (l >> k) & 1;
#pragma unroll
            for (int i = 0; i < (32 >> (k + 1)); i++) {
                float A = acc[2 * i], B = acc[2 * i + 1];
                float keep = s ? B : A;
                float send = s ? A : B;
                acc[i] = keep + __shfl_xor_sync(0xffffffffu, send, m);
            }
        }
        float rec = acc[0];

        // ---- scalar state update (owner thread) ----
        float inx = 0.f, zt = 0.f;
#pragma unroll
        for (int i = 0; i < NIN; i++)  inx = fmaf(sX[b * 8 + i], sWi[jl * 8 + i], inx);
#pragma unroll
        for (int o = 0; o < NOUT; o++) zt = fmaf(sZ[b * 8 + o], sWz[jl * 8 + o], zt);
        float rN = r + (__fdiv_rn(1.0f - r, sTa[jl]) - BETAC * r * hT) * DTC;
        float dh = __fdiv_rn(rec + inx + zt - h, TAUC);
        float hN = h + dh * DTC;
        float hTN = my_tanh(hN);

        size_t oidx = ((size_t)b * Tdim + t) * Hdim + jrow + jl;
        out_h[oidx] = hN;
        out_r[oidx] = rN;
        __stcg(&g_v[nb][b * Hdim + jrow + jl], rN * hTN);
        sHT[jl * 16 + b] = hTN;
        h = hN; r = rN; hT = hTN;
        __syncthreads();

        if (tid < 128) {
            int bb2 = tid >> 3, oo = tid & 7;
            float s = 0.f;
#pragma unroll
            for (int j2 = 0; j2 < RPC; j2++) s = fmaf(sHT[j2 * 16 + bb2], sWo[oo * 16 + j2], s);
            __stcg(&g_zp[nb][cta * 128 + tid], s);
        }
        gbar((unsigned)t + 2u);
    }

    // ---- final z output (z_{T-1}) ----
    if (cta == 0 && tid < 128) {
        const float* zp = g_zp[Tdim & 1] + tid;
        float s = 0.f;
#pragma unroll 8
        for (int c2 = 0; c2 < NCTA; c2++) s += __ldcg(zp + c2 * 128);
        out_z[((size_t)(tid >> 3) * Tdim + (Tdim - 1)) * NOUT + (tid & 7)] = s;
    }
}

extern "C" void kernel_launch(void* const* d_in, const int* in_sizes, int n_in,
                              void* d_out, int out_size) {
    const float* x   = (const float*)d_in[0];
    const float* h0  = (const float*)d_in[1];
    const float* Wih = (const float*)d_in[2];
    const float* Wt  = (const float*)d_in[3];
    const float* Wf  = (const float*)d_in[4];
    const float* mk  = (const float*)d_in[5];
    const float* Whz = (const float*)d_in[6];
    const float* Wzh = (const float*)d_in[7];
    const float* tau = (const float*)d_in[8];
    float* out = (float*)d_out;

    build_wm<<<(Hdim * Hdim + 255) / 256, 256>>>(Wt, Wf, mk);

    cudaFuncSetAttribute(rnn_persist, cudaFuncAttributeMaxDynamicSharedMemorySize, 50064 * 4);
    rnn_persist<<<NCTA, NTH, 50064 * 4>>>(x, h0, Wih, Whz, Wzh, tau, out);
}

// round 3
// speedup vs baseline: 1.3754x; 1.3754x over previous
#include <cuda_runtime.h>
#include <cstdint>
#include <math.h>

#define Hdim 2048
#define Bdim 16
#define Tdim 1024
#define NIN 8
#define NOUT 8
#define TUNED 10
#define NCTA 128
#define RPC 16
#define NTH 256
#define KC 512
#define NCH 4
#define DTC 0.001f
#define TAUC 0.01f
#define BETAC 1.5f

typedef unsigned long long u64;

// ---- device-global scratch (static allocations allowed) ----
__device__ float g_Wm[Hdim * Hdim];                 // masked recurrent weights [j][k]
__device__ float g_v[2][Bdim * Hdim];               // v = r*tanh(h), double buffered
__device__ float g_zt[Tdim * NCTA * 128];           // per-step per-CTA z partials (output path)
__device__ float g_zp0[NCTA * 128];                 // init z partials (fallback only)
__device__ unsigned g_wcnt[4];                      // per-k-chunk producer counters (monotonic)
__device__ unsigned g_rcnt;                         // consumer counter (monotonic)
__device__ unsigned g_zcnt;                         // fallback z counter
__device__ int g_zflag;                             // 1 if W_zh has any nonzero

__device__ __forceinline__ void cp16(float* d, const float* s) {
    unsigned ds = (unsigned)__cvta_generic_to_shared(d);
    asm volatile("cp.async.cg.shared.global [%0],[%1],16;" ::"r"(ds), "l"(s));
}
__device__ __forceinline__ unsigned ldacq(const unsigned* p) {
    unsigned v;
    asm volatile("ld.acquire.gpu.u32 %0,[%1];" : "=r"(v) : "l"(p));
    return v;
}
__device__ __forceinline__ u64 fma2(u64 a, u64 b, u64 c) {
    u64 d;
    asm("fma.rn.f32x2 %0,%1,%2,%3;" : "=l"(d) : "l"(a), "l"(b), "l"(c));
    return d;
}
__device__ __forceinline__ float unpack_sum(u64 v) {
    float lo, hi;
    asm("mov.b64 {%0,%1},%2;" : "=f"(lo), "=f"(hi) : "l"(v));
    return lo + hi;
}
// accurate tanh independent of fast-math: tanh(x)=sign(x)*(1-2/(e^{2|x|}+1))
__device__ __forceinline__ float my_tanh(float x) {
    float ax = fabsf(x);
    float e;
    asm("ex2.approx.f32 %0, %1;" : "=f"(e) : "f"(ax * 2.8853900817779268f));
    float r = 1.0f - __fdiv_rn(2.0f, e + 1.0f);
    return x < 0.0f ? -r : r;
}
// 5-level merge reduce: lane l ends with total of index l in a[0]
__device__ __forceinline__ float merge32(float* a, int l) {
#pragma unroll
    for (int k = 0; k < 5; k++) {
        const int m = 1 << k;
        const bool s = (l >> k) & 1;
#pragma unroll
        for (int i = 0; i < (32 >> (k + 1)); i++) {
            float A = a[2 * i], B = a[2 * i + 1];
            float keep = s ? B : A;
            float send = s ? A : B;
            a[i] = keep + __shfl_xor_sync(0xffffffffu, send, m);
        }
    }
    return a[0];
}

__global__ void reset_counters() {
    g_wcnt[0] = 0u; g_wcnt[1] = 0u; g_wcnt[2] = 0u; g_wcnt[3] = 0u;
    g_rcnt = 0u; g_zcnt = 0u; g_zflag = 0;
}
__global__ void scan_wzh(const float* __restrict__ wzh) {
    int i = blockIdx.x * 256 + threadIdx.x;
    if (i < Hdim * NOUT && wzh[i] != 0.0f) g_zflag = 1;
}
__global__ void build_wm(const float* __restrict__ wt, const float* __restrict__ wf,
                         const float* __restrict__ mk) {
    int idx = blockIdx.x * 256 + threadIdx.x;
    if (idx < Hdim * Hdim) {
        int j = idx >> 11, k = idx & (Hdim - 1);
        float w = (k < TUNED) ? wt[j * TUNED + k] : wf[j * (Hdim - TUNED) + (k - TUNED)];
        g_Wm[idx] = mk[idx] * w;
    }
}
// final cross-CTA z reduction (off critical path)
__global__ void zred(float* __restrict__ out_z) {
    int idx = blockIdx.x * 256 + threadIdx.x;   // 131072 = 1024 * 128
    int t = idx >> 7, bo = idx & 127;
    const float* p = g_zt + (size_t)t * (NCTA * 128) + bo;
    float s = 0.f;
#pragma unroll 8
    for (int c = 0; c < NCTA; c++) s += __ldcg(p + c * 128);
    out_z[((size_t)(bo >> 3) * Tdim + t) * NOUT + (bo & 7)] = s;
}

__device__ __forceinline__ void prefetch(float* sV, const float* vsrc, int c, int tid) {
    float* dst = sV + (c & 1) * (Bdim * KC);
    const float* src = vsrc + c * KC;
#pragma unroll
    for (int u = 0; u < 8; u++) {
        int seg = u * NTH + tid;          // 2048 segments of 16B
        int b = seg >> 7;
        int f = (seg & 127) << 2;
        cp16(dst + b * KC + f, src + (size_t)b * Hdim + f);
    }
    asm volatile("cp.async.commit_group;" ::: "memory");
}

__global__ __launch_bounds__(NTH, 1) void rnn_persist(
    const float* __restrict__ x, const float* __restrict__ h0,
    const float* __restrict__ Wih, const float* __restrict__ Whz,
    const float* __restrict__ Wzh, const float* __restrict__ tau,
    float* __restrict__ out) {

    extern __shared__ float sm[];
    float* sWm = sm;              // 32768
    float* sV  = sm + 32768;      // 16384
    float* sHT = sm + 49152;      // 256  [j*16+b]
    float* sZ  = sm + 49408;      // 128  [b*8+o] (fallback)
    float* sX  = sm + 49536;      // 128  [b*8+i]
    float* sWi = sm + 49664;      // 128  [j*8+i]
    float* sWz = sm + 49792;      // 128  [j*8+o]
    float* sWo = sm + 49920;      // 128  [o*16+j]
    float* sTa = sm + 50048;      // 16
    float* sP  = sm + 50064;      // 512  [kg*256 + cell]

    const int tid = threadIdx.x;
    const int cta = blockIdx.x;
    const int l = tid & 31, w = tid >> 5;
    // warp tiling: 2 row-groups x 2 batch-groups x 2 k-groups
    const int rg = w & 1, bg = (w >> 1) & 1, kg = w >> 2;
    const int jbase = rg * 8, bbase = bg * 8, kgo = kg * 256;
    // state ownership: thread tid owns cell (jl, b)
    const int jl = tid >> 4, b = tid & 15;
    const int jrow = cta * RPC;
    const int zf = g_zflag;

    float* out_z = out;
    float* out_h = out + (size_t)Bdim * Tdim * NOUT;
    float* out_r = out_h + (size_t)Bdim * Tdim * Hdim;
    (void)out_z;

    // ---- one-time loads ----
    {
        const float4* src = (const float4*)(g_Wm + (size_t)jrow * Hdim);
        float4* dst = (float4*)sWm;
#pragma unroll 8
        for (int i = tid; i < RPC * Hdim / 4; i += NTH) dst[i] = src[i];
    }
    if (tid < 128) {
        int jj = tid >> 3, ii = tid & 7;
        sWi[tid] = Wih[(jrow + jj) * NIN + ii];
        sWz[tid] = Wzh[(jrow + jj) * NOUT + ii];
        int oo = tid >> 4, j2 = tid & 15;
        sWo[tid] = Whz[oo * Hdim + jrow + j2];
    }
    if (tid < RPC) sTa[tid] = tau[jrow + tid];

    // ---- init state (registers, one cell per thread) ----
    float h = h0[(size_t)b * Hdim + jrow + jl];
    float r = 1.0f;
    float hT = my_tanh(h);
    __stcg(&g_v[0][b * Hdim + jrow + jl], hT);    // r0=1 -> v0 = tanh(h0)
    sHT[jl * 16 + b] = hT;
    __syncthreads();
    if (zf && tid < 128) {  // init z partial (fallback feedback only)
        int bb2 = tid >> 3, oo = tid & 7;
        float s = 0.f;
#pragma unroll
        for (int j2 = 0; j2 < RPC; j2++) s = fmaf(sHT[j2 * 16 + bb2], sWo[oo * 16 + j2], s);
        __stcg(&g_zp0[cta * 128 + tid], s);
    }
    __syncthreads();
    if (tid == 0) {
        __threadfence();
        atomicAdd(&g_wcnt[cta >> 5], 1u);
        if (zf) atomicAdd(&g_zcnt, 1u);
    }

    // ---- time loop ----
    for (int t = 0; t < Tdim; t++) {
        const int cb = t & 1, nb = cb ^ 1;
        const float* vsrc = g_v[cb];

        // wait for all producers of this step's v (4 independent acquire loads)
        if (tid == 0) {
            const unsigned tgt = 32u * (unsigned)(t + 1);
            while (ldacq(&g_wcnt[0]) < tgt) {}
            while (ldacq(&g_wcnt[1]) < tgt) {}
            while (ldacq(&g_wcnt[2]) < tgt) {}
            while (ldacq(&g_wcnt[3]) < tgt) {}
            if (zf) {
                const unsigned zt_ = 128u * (unsigned)(t + 1);
                while (ldacq(&g_zcnt) < zt_) {}
            }
        }
        __syncthreads();
        prefetch(sV, vsrc, 0, tid);

        if (tid < 128) {
            sX[tid] = x[((size_t)(tid >> 3) * Tdim + t) * NIN + (tid & 7)];
            if (zf) {  // fallback: reduce z_{t-1} for feedback
                const float* zp = (t == 0) ? (g_zp0 + tid)
                                           : (g_zt + (size_t)(t - 1) * (NCTA * 128) + tid);
                float s = 0.f;
#pragma unroll 8
                for (int c2 = 0; c2 < NCTA; c2++) s += __ldcg(zp + c2 * 128);
                sZ[tid] = s;
            }
        }

        // ---- matvec: 8 rows x 8 batches per thread, f32x2 FMA, k-split 32x2 ----
        u64 acc[64];
#pragma unroll
        for (int i = 0; i < 64; i++) acc[i] = 0ull;

        for (int c = 0; c < NCH; c++) {
            asm volatile("cp.async.wait_group 0;" ::: "memory");
            __syncthreads();
            if (c + 1 < NCH) prefetch(sV, vsrc, c + 1, tid);
            if (c == NCH - 1 && tid == 0) {
                atomicAdd(&g_rcnt, 1u);   // my reads of v[cb] are complete
                if (t > 0) {              // all CTAs done reading v[nb] (step t-1)?
                    const unsigned tg = 128u * (unsigned)t;
                    while (ldacq(&g_rcnt) < tg) {}
                }
            }
            const float* Wp = sWm + jbase * Hdim + c * KC + kgo + (l << 2);
            const float* Vp = sV + (c & 1) * (Bdim * KC) + bbase * KC + kgo + (l << 2);
#pragma unroll
            for (int it = 0; it < 2; it++) {
                ulonglong2 wv[8], vv[8];
#pragma unroll
                for (int rr = 0; rr < 8; rr++)
                    wv[rr] = *(const ulonglong2*)(Wp + rr * Hdim + it * 128);
#pragma unroll
                for (int q = 0; q < 8; q++)
                    vv[q] = *(const ulonglong2*)(Vp + q * KC + it * 128);
#pragma unroll
                for (int rr = 0; rr < 8; rr++)
#pragma unroll
                    for (int q = 0; q < 8; q++) {
                        u64 A = acc[rr * 8 + q];
                        A = fma2(wv[rr].x, vv[q].x, A);
                        A = fma2(wv[rr].y, vv[q].y, A);
                        acc[rr * 8 + q] = A;
                    }
            }
            __syncthreads();
        }

        // ---- reduce: per-warp shfl merge, then cross-kg combine via smem ----
        {
            float a[32];
#pragma unroll
            for (int i = 0; i < 32; i++) a[i] = unpack_sum(acc[i]);
            float recA = merge32(a, l);               // rows jbase..jbase+3
#pragma unroll
            for (int i = 0; i < 32; i++) a[i] = unpack_sum(acc[32 + i]);
            float recB = merge32(a, l);               // rows jbase+4..jbase+7
            int cellA = (jbase + (l >> 3)) * 16 + bbase + (l & 7);
            sP[kg * 256 + cellA] = recA;
            sP[kg * 256 + cellA + 64] = recB;         // +4 rows -> +64 cells
        }
        __syncthreads();

        // ---- state update (owner thread per cell) ----
        {
            float rec = sP[tid] + sP[256 + tid];
            float inx = 0.f, zt = 0.f;
#pragma unroll
            for (int i = 0; i < NIN; i++) inx = fmaf(sX[b * 8 + i], sWi[jl * 8 + i], inx);
            if (zf) {
#pragma unroll
                for (int o = 0; o < NOUT; o++) zt = fmaf(sZ[b * 8 + o], sWz[jl * 8 + o], zt);
            }
            float rN = r + (__fdiv_rn(1.0f - r, sTa[jl]) - BETAC * r * hT) * DTC;
            float dh = __fdiv_rn(rec + inx + zt - h, TAUC);
            float hN = h + dh * DTC;
            float hTN = my_tanh(hN);

            size_t oidx = ((size_t)b * Tdim + t) * Hdim + jrow + jl;
            out_h[oidx] = hN;
            out_r[oidx] = rN;
            __stcg(&g_v[nb][b * Hdim + jrow + jl], rN * hTN);
            sHT[jl * 16 + b] = hTN;
            h = hN; r = rN; hT = hTN;
        }
        __syncthreads();

        // z partial for this step (output path; also fallback feedback source)
        if (tid < 128) {
            int bb2 = tid >> 3, oo = tid & 7;
            float s = 0.f;
#pragma unroll
            for (int j2 = 0; j2 < RPC; j2++) s = fmaf(sHT[j2 * 16 + bb2], sWo[oo * 16 + j2], s);
            __stcg(&g_zt[(size_t)t * (NCTA * 128) + cta * 128 + tid], s);
        }
        if (tid == 0) {
            __threadfence();
            atomicAdd(&g_wcnt[cta >> 5], 1u);   // release: v[nb] published
            if (zf) atomicAdd(&g_zcnt, 1u);
        }
    }
}

extern "C" void kernel_launch(void* const* d_in, const int* in_sizes, int n_in,
                              void* d_out, int out_size) {
    const float* x   = (const float*)d_in[0];
    const float* h0  = (const float*)d_in[1];
    const float* Wih = (const float*)d_in[2];
    const float* Wt  = (const float*)d_in[3];
    const float* Wf  = (const float*)d_in[4];
    const float* mk  = (const float*)d_in[5];
    const float* Whz = (const float*)d_in[6];
    const float* Wzh = (const float*)d_in[7];
    const float* tau = (const float*)d_in[8];
    float* out = (float*)d_out;

    reset_counters<<<1, 1>>>();
    scan_wzh<<<(Hdim * NOUT + 255) / 256, 256>>>(Wzh);
    build_wm<<<(Hdim * Hdim + 255) / 256, 256>>>(Wt, Wf, mk);

    cudaFuncSetAttribute(rnn_persist, cudaFuncAttributeMaxDynamicSharedMemorySize, 50576 * 4);
    rnn_persist<<<NCTA, NTH, 50576 * 4>>>(x, h0, Wih, Whz, Wzh, tau, out);

    zred<<<(Tdim * 128) / 256, 256>>>(out);
}

// round 4
// speedup vs baseline: 1.4545x; 1.0575x over previous
#include <cuda_runtime.h>
#include <cstdint>
#include <math.h>

#define Hdim 2048
#define Bdim 16
#define Tdim 1024
#define NIN 8
#define NOUT 8
#define TUNED 10
#define NCTA 128
#define RPC 16
#define NTH 256
#define KC 512
#define NCH 4
#define DTC 0.001f
#define BETAC 1.5f

typedef unsigned long long u64;

// ---- device-global scratch (static allocations allowed) ----
__device__ float g_Wm[Hdim * Hdim];                 // masked recurrent weights [j][k]
__device__ float g_v[2][Bdim * Hdim];               // v = r*tanh(h), double buffered
__device__ float g_zt[Tdim * NCTA * 128];           // per-step per-CTA z partials
__device__ float g_zp0[NCTA * 128];                 // init z partials (fallback only)
__device__ unsigned g_wcnt[4];                      // per-group producer counters (monotonic)
__device__ unsigned g_rcnt;                         // consumer counter (monotonic)
__device__ unsigned g_zcnt;                         // fallback z counter
__device__ int g_zflag;                             // 1 if W_zh has any nonzero

__device__ __forceinline__ void cp16(float* d, const float* s) {
    unsigned ds = (unsigned)__cvta_generic_to_shared(d);
    asm volatile("cp.async.cg.shared.global [%0],[%1],16;" ::"r"(ds), "l"(s));
}
__device__ __forceinline__ unsigned ldacq(const unsigned* p) {
    unsigned v;
    asm volatile("ld.acquire.gpu.u32 %0,[%1];" : "=r"(v) : "l"(p));
    return v;
}
__device__ __forceinline__ u64 fma2(u64 a, u64 b, u64 c) {
    u64 d;
    asm("fma.rn.f32x2 %0,%1,%2,%3;" : "=l"(d) : "l"(a), "l"(b), "l"(c));
    return d;
}
__device__ __forceinline__ float unpack_sum(u64 v) {
    float lo, hi;
    asm("mov.b64 {%0,%1},%2;" : "=f"(lo), "=f"(hi) : "l"(v));
    return lo + hi;
}
// tanh(x)=sign(x)*(1-2/(e^{2|x|}+1)); rcp.approx + 1 Newton step (~1e-7 rel)
__device__ __forceinline__ float my_tanh(float x) {
    float e;
    asm("ex2.approx.f32 %0, %1;" : "=f"(e) : "f"(fabsf(x) * 2.8853900817779268f));
    float y = e + 1.0f;
    float r0;
    asm("rcp.approx.f32 %0, %1;" : "=f"(r0) : "f"(y));
    r0 = r0 * fmaf(-y, r0, 2.0f);            // Newton refine
    float res = fmaf(-2.0f, r0, 1.0f);
    return copysignf(res, x);
}
// 5-level merge reduce: lane l ends with total of accumulator index l
__device__ __forceinline__ float merge32(float* a, int l) {
#pragma unroll
    for (int k = 0; k < 5; k++) {
        const int m = 1 << k;
        const bool s = (l >> k) & 1;
#pragma unroll
        for (int i = 0; i < (32 >> (k + 1)); i++) {
            float A = a[2 * i], B = a[2 * i + 1];
            float keep = s ? B : A;
            float send = s ? A : B;
            a[i] = keep + __shfl_xor_sync(0xffffffffu, send, m);
        }
    }
    return a[0];
}

__global__ void reset_counters() {
    g_wcnt[0] = 0u; g_wcnt[1] = 0u; g_wcnt[2] = 0u; g_wcnt[3] = 0u;
    g_rcnt = 0u; g_zcnt = 0u; g_zflag = 0;
}
__global__ void scan_wzh(const float* __restrict__ wzh) {
    int i = blockIdx.x * 256 + threadIdx.x;
    if (i < Hdim * NOUT && wzh[i] != 0.0f) g_zflag = 1;
}
__global__ void build_wm(const float* __restrict__ wt, const float* __restrict__ wf,
                         const float* __restrict__ mk) {
    int idx = blockIdx.x * 256 + threadIdx.x;
    if (idx < Hdim * Hdim) {
        int j = idx >> 11, k = idx & (Hdim - 1);
        float w = (k < TUNED) ? wt[j * TUNED + k] : wf[j * (Hdim - TUNED) + (k - TUNED)];
        g_Wm[idx] = mk[idx] * w;
    }
}
// final cross-CTA z reduction (off critical path)
__global__ void zred(float* __restrict__ out_z) {
    int idx = blockIdx.x * 256 + threadIdx.x;
    int t = idx >> 7, bo = idx & 127;
    const float* p = g_zt + (size_t)t * (NCTA * 128) + bo;
    float s = 0.f;
#pragma unroll 8
    for (int c = 0; c < NCTA; c++) s += __ldcg(p + c * 128);
    out_z[((size_t)(bo >> 3) * Tdim + t) * NOUT + (bo & 7)] = s;
}

__device__ __forceinline__ void prefetch(float* sV, const float* vsrc, int slot, int c, int tid) {
    float* dst = sV + slot * (Bdim * KC);
    const float* src = vsrc + c * KC;
#pragma unroll
    for (int u = 0; u < 8; u++) {
        int seg = u * NTH + tid;          // 2048 segments of 16B
        int b = seg >> 7;
        int f = (seg & 127) << 2;
        cp16(dst + b * KC + f, src + (size_t)b * Hdim + f);
    }
    asm volatile("cp.async.commit_group;" ::: "memory");
}

__device__ __forceinline__ void chunk_fma(const float* sWm, const float* sV, u64* acc,
                                          int jbase, int bbase, int kgo, int l,
                                          int c, int slot) {
    const float* Wp = sWm + jbase * Hdim + c * KC + kgo + (l << 2);
    const float* Vp = sV + slot * (Bdim * KC) + bbase * KC + kgo + (l << 2);
#pragma unroll
    for (int it = 0; it < 2; it++) {
        ulonglong2 wv[8], vv[8];
#pragma unroll
        for (int rr = 0; rr < 8; rr++)
            wv[rr] = *(const ulonglong2*)(Wp + rr * Hdim + it * 128);
#pragma unroll
        for (int q = 0; q < 8; q++)
            vv[q] = *(const ulonglong2*)(Vp + q * KC + it * 128);
#pragma unroll
        for (int rr = 0; rr < 8; rr++)
#pragma unroll
            for (int q = 0; q < 8; q++) {
                u64 A = acc[rr * 8 + q];
                A = fma2(wv[rr].x, vv[q].x, A);
                A = fma2(wv[rr].y, vv[q].y, A);
                acc[rr * 8 + q] = A;
            }
    }
}

__global__ __launch_bounds__(NTH, 1) void rnn_persist(
    const float* __restrict__ x, const float* __restrict__ h0,
    const float* __restrict__ Wih, const float* __restrict__ Whz,
    const float* __restrict__ Wzh, const float* __restrict__ tau,
    float* __restrict__ out) {

    extern __shared__ float sm[];
    float* sWm = sm;              // 32768
    float* sV  = sm + 32768;      // 16384
    float* sHT = sm + 49152;      // 256  [j*16+b]
    float* sZ  = sm + 49408;      // 128  (fallback)
    float* sX  = sm + 49536;      // 128  [b*8+i]
    float* sWi = sm + 49664;      // 128  [j*8+i]
    float* sWz = sm + 49792;      // 128  [j*8+o]
    float* sWo = sm + 49920;      // 128  [o*16+j]
    float* sTa = sm + 50048;      // 16
    float* sP  = sm + 50064;      // 512  [kg*256 + cell]
    unsigned* sFlag = (unsigned*)(sm + 50576); // 4

    const int tid = threadIdx.x;
    const int cta = blockIdx.x;
    const int l = tid & 31, w = tid >> 5;
    const int rg = w & 1, bg = (w >> 1) & 1, kg = w >> 2;
    const int jbase = rg * 8, bbase = bg * 8, kgo = kg * 256;
    const int jl = tid >> 4, b = tid & 15;
    const int jrow = cta * RPC;
    const int myg = cta >> 5;
    const int zf = g_zflag;

    float* out_h = out + (size_t)Bdim * Tdim * NOUT;
    float* out_r = out_h + (size_t)Bdim * Tdim * Hdim;

    // ---- one-time loads ----
    {
        const float4* src = (const float4*)(g_Wm + (size_t)jrow * Hdim);
        float4* dst = (float4*)sWm;
#pragma unroll 8
        for (int i = tid; i < RPC * Hdim / 4; i += NTH) dst[i] = src[i];
    }
    if (tid < 128) {
        int jj = tid >> 3, ii = tid & 7;
        sWi[tid] = Wih[(jrow + jj) * NIN + ii];
        sWz[tid] = Wzh[(jrow + jj) * NOUT + ii];
        int oo = tid >> 4, j2 = tid & 15;
        sWo[tid] = Whz[oo * Hdim + jrow + j2];
    }
    if (tid < RPC) sTa[tid] = tau[jrow + tid];
    __syncthreads();

    // ---- init state (registers) ----
    const float itau = 1.0f / sTa[jl];
    float h = h0[(size_t)b * Hdim + jrow + jl];
    float r = 1.0f;
    float hT = my_tanh(h);
    __stcg(&g_v[0][b * Hdim + jrow + jl], hT);    // r0=1 -> v0 = tanh(h0)
    sHT[jl * 16 + b] = hT;
    __syncthreads();
    if (zf && tid < 128) {
        int bb2 = tid >> 3, oo = tid & 7;
        float s = 0.f;
#pragma unroll
        for (int j2 = 0; j2 < RPC; j2++) s = fmaf(sHT[j2 * 16 + bb2], sWo[oo * 16 + j2], s);
        __stcg(&g_zp0[cta * 128 + tid], s);
    }
    __syncthreads();
    if (tid == 0) {
        __threadfence();
        atomicAdd(&g_wcnt[myg], 1u);
        if (zf) atomicAdd(&g_zcnt, 1u);
    }

    const int c0 = myg, c1 = (myg + 1) & 3, c2 = (myg + 2) & 3, c3 = (myg + 3) & 3;

    // ---- time loop ----
    for (int t = 0; t < Tdim; t++) {
        const int cb = t & 1, nb = cb ^ 1;
        const float* vsrc = g_v[cb];
        const unsigned tgt = 32u * (unsigned)(t + 1);

        if (tid < 128) {
            sX[tid] = x[((size_t)(tid >> 3) * Tdim + t) * NIN + (tid & 7)];
            if (zf) {
                const float* zp = (t == 0) ? (g_zp0 + tid)
                                           : (g_zt + (size_t)(t - 1) * (NCTA * 128) + tid);
                float s = 0.f;
#pragma unroll 8
                for (int q = 0; q < NCTA; q++) s += __ldcg(zp + q * 128);
                sZ[tid] = s;
            }
        }
        // wait own group; snapshot the rest in one pipelined pass
        if (tid == 0) {
            while (ldacq(&g_wcnt[c0]) < tgt) {}
            unsigned a1 = ldacq(&g_wcnt[c1]);
            unsigned a2 = ldacq(&g_wcnt[c2]);
            unsigned a3 = ldacq(&g_wcnt[c3]);
            sFlag[1] = (a1 >= tgt); sFlag[2] = (a2 >= tgt); sFlag[3] = (a3 >= tgt);
            if (zf) {
                const unsigned zt_ = 128u * (unsigned)(t + 1);
                while (ldacq(&g_zcnt) < zt_) {}
            }
        }
        __syncthreads();
        prefetch(sV, vsrc, 0, c0, tid);
        if (tid == 0 && !sFlag[1]) { while (ldacq(&g_wcnt[c1]) < tgt) {} }
        __syncthreads();
        prefetch(sV, vsrc, 1, c1, tid);

        u64 acc[64];
#pragma unroll
        for (int i = 0; i < 64; i++) acc[i] = 0ull;

        // i = 0
        asm volatile("cp.async.wait_group 1;" ::: "memory");
        __syncthreads();
        chunk_fma(sWm, sV, acc, jbase, bbase, kgo, l, c0, 0);
        if (tid == 0 && !sFlag[2]) { while (ldacq(&g_wcnt[c2]) < tgt) {} }
        __syncthreads();
        prefetch(sV, vsrc, 0, c2, tid);
        // i = 1
        asm volatile("cp.async.wait_group 1;" ::: "memory");
        __syncthreads();
        chunk_fma(sWm, sV, acc, jbase, bbase, kgo, l, c1, 1);
        if (tid == 0 && !sFlag[3]) { while (ldacq(&g_wcnt[c3]) < tgt) {} }
        __syncthreads();
        prefetch(sV, vsrc, 1, c3, tid);
        // i = 2
        asm volatile("cp.async.wait_group 1;" ::: "memory");
        __syncthreads();
        chunk_fma(sWm, sV, acc, jbase, bbase, kgo, l, c2, 0);
        // i = 3
        asm volatile("cp.async.wait_group 0;" ::: "memory");
        __syncthreads();
        chunk_fma(sWm, sV, acc, jbase, bbase, kgo, l, c3, 1);

        // signal my reads done; ensure all CTAs done reading v[nb] (step t-1)
        if (tid == 0) {
            asm volatile("red.release.gpu.global.add.u32 [%0],1;" ::"l"(&g_rcnt) : "memory");
            if (t > 0) {
                const unsigned tg = 128u * (unsigned)t;
                while (ldacq(&g_rcnt) < tg) {}
            }
        }

        // ---- reduce: per-warp shfl merge, then cross-kg combine via smem ----
        {
            float a[32];
#pragma unroll
            for (int i = 0; i < 32; i++) a[i] = unpack_sum(acc[i]);
            float recA = merge32(a, l);
#pragma unroll
            for (int i = 0; i < 32; i++) a[i] = unpack_sum(acc[32 + i]);
            float recB = merge32(a, l);
            int cellA = (jbase + (l >> 3)) * 16 + bbase + (l & 7);
            sP[kg * 256 + cellA] = recA;
            sP[kg * 256 + cellA + 64] = recB;
        }
        __syncthreads();

        // ---- state update (owner thread per cell) ----
        {
            float rec = sP[tid] + sP[256 + tid];
            float inx = 0.f, zt = 0.f;
#pragma unroll
            for (int i = 0; i < NIN; i++) inx = fmaf(sX[b * 8 + i], sWi[jl * 8 + i], inx);
            if (zf) {
#pragma unroll
                for (int o = 0; o < NOUT; o++) zt = fmaf(sZ[b * 8 + o], sWz[jl * 8 + o], zt);
            }
            float rs = fmaf(-BETAC * r, hT, (1.0f - r) * itau);
            float rN = fmaf(rs, DTC, r);
            float s = rec + inx + zt - h;
            float hN = fmaf(s, 0.1f, h);          // (s/TAU)*DT = s*0.1
            float hTN = my_tanh(hN);

            size_t oidx = ((size_t)b * Tdim + t) * Hdim + jrow + jl;
            out_h[oidx] = hN;
            out_r[oidx] = rN;
            __stcg(&g_v[nb][b * Hdim + jrow + jl], rN * hTN);
            sHT[jl * 16 + b] = hTN;
            h = hN; r = rN; hT = hTN;
        }
        __syncthreads();

        // release v[nb] first (critical path), then z partial (off path when !zf)
        if (tid == 0) {
            __threadfence();
            atomicAdd(&g_wcnt[myg], 1u);
        }
        if (tid < 128) {
            int bb2 = tid >> 3, oo = tid & 7;
            float s = 0.f;
#pragma unroll
            for (int j2 = 0; j2 < RPC; j2++) s = fmaf(sHT[j2 * 16 + bb2], sWo[oo * 16 + j2], s);
            __stcg(&g_zt[(size_t)t * (NCTA * 128) + cta * 128 + tid], s);
        }
        if (zf) {
            __syncthreads();
            if (tid == 0) { __threadfence(); atomicAdd(&g_zcnt, 1u); }
        }
    }
}

extern "C" void kernel_launch(void* const* d_in, const int* in_sizes, int n_in,
                              void* d_out, int out_size) {
    const float* x   = (const float*)d_in[0];
    const float* h0  = (const float*)d_in[1];
    const float* Wih = (const float*)d_in[2];
    const float* Wt  = (const float*)d_in[3];
    const float* Wf  = (const float*)d_in[4];
    const float* mk  = (const float*)d_in[5];
    const float* Whz = (const float*)d_in[6];
    const float* Wzh = (const float*)d_in[7];
    const float* tau = (const float*)d_in[8];
    float* out = (float*)d_out;

    reset_counters<<<1, 1>>>();
    scan_wzh<<<(Hdim * NOUT + 255) / 256, 256>>>(Wzh);
    build_wm<<<(Hdim * Hdim + 255) / 256, 256>>>(Wt, Wf, mk);

    cudaFuncSetAttribute(rnn_persist, cudaFuncAttributeMaxDynamicSharedMemorySize, 50580 * 4);
    rnn_persist<<<NCTA, NTH, 50580 * 4>>>(x, h0, Wih, Whz, Wzh, tau, out);

    zred<<<(Tdim * 128) / 256, 256>>>(out);
}